// round 1
// baseline (speedup 1.0000x reference)
#include <cuda_runtime.h>
#include <math.h>

#define T_SEQ 2048
#define DMODEL 2048
#define NH 32
#define NKV 8
#define HD 64

// Scratch (device globals: allocation-free per harness rules)
__device__ float g_q[(size_t)2 * NH * T_SEQ * HD];    // (b, h, t, d)
__device__ float g_ctx[(size_t)2 * T_SEQ * NH * HD];  // (b, t, h, d)

// ---------------------------------------------------------------------------
// Generic SGEMM: C = A(MxK) * W(NxK)^T + bias, with fused epilogues.
// MODE 0: A := g_ctx, plain write C[m*N+n]            (output projection)
// MODE 1: RoPE, write g_q as (b, h, t, d)             (Q projection)
// MODE 2: RoPE, write C as (b, kv, t, d)              (K projection)
// MODE 3: plain, write C as (b, kv, t, d)             (V projection)
// ---------------------------------------------------------------------------
#define GBM 128
#define GBN 128
#define GBK 16

template <int MODE>
__global__ __launch_bounds__(256) void gemm_kernel(
    const float* __restrict__ A, const float* __restrict__ W,
    const float* __restrict__ bias, float* __restrict__ C,
    const float* __restrict__ cosT, const float* __restrict__ sinT,
    int M, int N, int K)
{
    __shared__ float As[GBK][GBM];
    __shared__ float Ws[GBK][GBN];

    const float* Ap = (MODE == 0) ? g_ctx : A;

    int tid = threadIdx.x;
    int tx = tid & 15;
    int ty = tid >> 4;
    int m0 = blockIdx.y * GBM;
    int n0 = blockIdx.x * GBN;

    float acc[8][8];
#pragma unroll
    for (int i = 0; i < 8; i++)
#pragma unroll
        for (int j = 0; j < 8; j++) acc[i][j] = 0.f;

    for (int k0 = 0; k0 < K; k0 += GBK) {
        // Load A tile (128x16) and W tile (128x16), 512 float4 each.
#pragma unroll
        for (int it = 0; it < 2; it++) {
            int lin = it * 256 + tid;
            int row = lin >> 2;
            int col4 = (lin & 3) << 2;
            float4 av = *(const float4*)&Ap[(size_t)(m0 + row) * K + k0 + col4];
            As[col4 + 0][row] = av.x;
            As[col4 + 1][row] = av.y;
            As[col4 + 2][row] = av.z;
            As[col4 + 3][row] = av.w;
            float4 wv = *(const float4*)&W[(size_t)(n0 + row) * K + k0 + col4];
            Ws[col4 + 0][row] = wv.x;
            Ws[col4 + 1][row] = wv.y;
            Ws[col4 + 2][row] = wv.z;
            Ws[col4 + 3][row] = wv.w;
        }
        __syncthreads();

#pragma unroll
        for (int kk = 0; kk < GBK; kk++) {
            float ra[8], rb[8];
            *(float4*)&ra[0] = *(const float4*)&As[kk][ty * 8 + 0];
            *(float4*)&ra[4] = *(const float4*)&As[kk][ty * 8 + 4];
            *(float4*)&rb[0] = *(const float4*)&Ws[kk][tx * 8 + 0];
            *(float4*)&rb[4] = *(const float4*)&Ws[kk][tx * 8 + 4];
#pragma unroll
            for (int i = 0; i < 8; i++)
#pragma unroll
                for (int j = 0; j < 8; j++) acc[i][j] += ra[i] * rb[j];
        }
        __syncthreads();
    }

    // Epilogue
#pragma unroll
    for (int i = 0; i < 8; i++) {
        int m = m0 + ty * 8 + i;
        int b = m >> 11;          // m / T_SEQ
        int t = m & (T_SEQ - 1);  // m % T_SEQ
        if (MODE == 0) {
#pragma unroll
            for (int j = 0; j < 8; j++) {
                int n = n0 + tx * 8 + j;
                C[(size_t)m * N + n] = acc[i][j] + bias[n];
            }
        } else if (MODE == 3) {
#pragma unroll
            for (int j = 0; j < 8; j++) {
                int n = n0 + tx * 8 + j;
                int head = n >> 6;
                int d = n & 63;
                C[(((size_t)(b * NKV + head)) * T_SEQ + t) * HD + d] =
                    acc[i][j] + bias[n];
            }
        } else {
            // RoPE modes (1: Q, 2: K)
#pragma unroll
            for (int j = 0; j < 8; j += 2) {
                int n = n0 + tx * 8 + j;
                int head = n >> 6;
                int d = n & 63;
                int half = d >> 1;
                float c = cosT[t * (HD / 2) + half];
                float s = sinT[t * (HD / 2) + half];
                float x1 = acc[i][j] + bias[n];
                float x2 = acc[i][j + 1] + bias[n + 1];
                float e = x1 * c - x2 * s;
                float od = x1 * s + x2 * c;
                if (MODE == 1) {
                    float* dst = g_q + (((size_t)(b * NH + head)) * T_SEQ + t) * HD + d;
                    dst[0] = e;
                    dst[1] = od;
                } else {
                    float* dst = C + (((size_t)(b * NKV + head)) * T_SEQ + t) * HD + d;
                    dst[0] = e;
                    dst[1] = od;
                }
            }
        }
    }
}

// ---------------------------------------------------------------------------
// Causal GQA flash attention (fp32).
// grid = (T/64, B*H). block = 256 (64 rows x 4 "quads"; each quad owns 16
// score columns / 16 output dims). Online softmax with width-4 shuffles.
// K stored dim-major (Kt[k][s]) and Q dim-major (Qt[k][r]) in smem for
// conflict-free reads; V natural (Vs[s][d]) for float4 reads in PV.
// ---------------------------------------------------------------------------
__global__ __launch_bounds__(256) void attn_kernel(const float* __restrict__ Kg,
                                                   const float* __restrict__ Vg)
{
    __shared__ float Qt[64 * 64];
    __shared__ float Kt[64 * 64];
    __shared__ float Vs[64 * 64];

    int tid = threadIdx.x;
    int r = tid >> 2;    // row in q tile
    int quad = tid & 3;  // which 16-column slice

    int qi = blockIdx.x;
    int bh = blockIdx.y;
    int b = bh >> 5;
    int h = bh & 31;
    int kvh = h >> 2;

    const float* Qg = g_q + (((size_t)(b * NH + h)) * T_SEQ + qi * 64) * HD;
    const float* Kb = Kg + ((size_t)(b * NKV + kvh)) * T_SEQ * HD;
    const float* Vb = Vg + ((size_t)(b * NKV + kvh)) * T_SEQ * HD;

    // Load Q transposed: Qt[d][r]. Conflict-free smem stores (consecutive r per lane).
#pragma unroll
    for (int it = 0; it < 4; it++) {
        int lin = it * 256 + tid;        // float4 index 0..1023
        int d4 = (lin >> 6) << 2;        // (lin/64)*4
        int rr = lin & 63;
        float4 v = *(const float4*)&Qg[rr * HD + d4];
        Qt[(d4 + 0) * 64 + rr] = v.x;
        Qt[(d4 + 1) * 64 + rr] = v.y;
        Qt[(d4 + 2) * 64 + rr] = v.z;
        Qt[(d4 + 3) * 64 + rr] = v.w;
    }

    float o[16];
#pragma unroll
    for (int j = 0; j < 16; j++) o[j] = 0.f;
    float mrun = -INFINITY;
    float lrun = 0.f;

    for (int jt = 0; jt <= qi; jt++) {
        __syncthreads();  // protect Kt/Vs from previous iteration readers
        const float* Kp = Kb + (size_t)jt * 64 * HD;
        const float* Vp = Vb + (size_t)jt * 64 * HD;
#pragma unroll
        for (int it = 0; it < 4; it++) {
            int lin = it * 256 + tid;
            int d4 = (lin >> 6) << 2;
            int rr = lin & 63;
            float4 kv = *(const float4*)&Kp[rr * HD + d4];
            Kt[(d4 + 0) * 64 + rr] = kv.x;
            Kt[(d4 + 1) * 64 + rr] = kv.y;
            Kt[(d4 + 2) * 64 + rr] = kv.z;
            Kt[(d4 + 3) * 64 + rr] = kv.w;
            float4 vv = *(const float4*)&Vp[rr * HD + d4];
            *(float4*)&Vs[rr * 64 + d4] = vv;
        }
        __syncthreads();

        // S = Q K^T for this tile: each thread computes 16 columns of its row.
        float p[16];
#pragma unroll
        for (int j = 0; j < 16; j++) p[j] = 0.f;
        const float* KtQ = Kt + quad * 16;
#pragma unroll 8
        for (int k = 0; k < 64; k++) {
            float qv = Qt[k * 64 + r];
            float4 a0 = *(const float4*)&KtQ[k * 64 + 0];
            float4 a1 = *(const float4*)&KtQ[k * 64 + 4];
            float4 a2 = *(const float4*)&KtQ[k * 64 + 8];
            float4 a3 = *(const float4*)&KtQ[k * 64 + 12];
            p[0] += qv * a0.x;  p[1] += qv * a0.y;  p[2] += qv * a0.z;  p[3] += qv * a0.w;
            p[4] += qv * a1.x;  p[5] += qv * a1.y;  p[6] += qv * a1.z;  p[7] += qv * a1.w;
            p[8] += qv * a2.x;  p[9] += qv * a2.y;  p[10] += qv * a2.z; p[11] += qv * a2.w;
            p[12] += qv * a3.x; p[13] += qv * a3.y; p[14] += qv * a3.z; p[15] += qv * a3.w;
        }

        // scale + causal mask + online softmax
        bool diag = (jt == qi);
        float smax = -INFINITY;
#pragma unroll
        for (int j = 0; j < 16; j++) {
            float sv = p[j] * 0.125f;  // 1/sqrt(64)
            if (diag && (quad * 16 + j) > r) sv = -INFINITY;
            p[j] = sv;
            smax = fmaxf(smax, sv);
        }
        smax = fmaxf(smax, __shfl_xor_sync(0xffffffffu, smax, 1, 4));
        smax = fmaxf(smax, __shfl_xor_sync(0xffffffffu, smax, 2, 4));
        float mnew = fmaxf(mrun, smax);
        float alpha = __expf(mrun - mnew);
        float ls = 0.f;
#pragma unroll
        for (int j = 0; j < 16; j++) {
            p[j] = __expf(p[j] - mnew);
            ls += p[j];
        }
        ls += __shfl_xor_sync(0xffffffffu, ls, 1, 4);
        ls += __shfl_xor_sync(0xffffffffu, ls, 2, 4);
        lrun = lrun * alpha + ls;
        mrun = mnew;
#pragma unroll
        for (int j = 0; j < 16; j++) o[j] *= alpha;

        // PV: o[d] += sum_s p[s] * V[s][d]; p exchanged via width-4 shuffles.
        const float* VsQ = Vs + quad * 16;
#pragma unroll
        for (int s = 0; s < 64; s++) {
            float pv = __shfl_sync(0xffffffffu, p[s & 15], s >> 4, 4);
            float4 v0 = *(const float4*)&VsQ[s * 64 + 0];
            float4 v1 = *(const float4*)&VsQ[s * 64 + 4];
            float4 v2 = *(const float4*)&VsQ[s * 64 + 8];
            float4 v3 = *(const float4*)&VsQ[s * 64 + 12];
            o[0] += pv * v0.x;  o[1] += pv * v0.y;  o[2] += pv * v0.z;  o[3] += pv * v0.w;
            o[4] += pv * v1.x;  o[5] += pv * v1.y;  o[6] += pv * v1.z;  o[7] += pv * v1.w;
            o[8] += pv * v2.x;  o[9] += pv * v2.y;  o[10] += pv * v2.z; o[11] += pv * v2.w;
            o[12] += pv * v3.x; o[13] += pv * v3.y; o[14] += pv * v3.z; o[15] += pv * v3.w;
        }
    }

    float inv = 1.0f / lrun;
    int t = qi * 64 + r;
    float* op = g_ctx + (((size_t)(b * T_SEQ + t)) * NH + h) * HD + quad * 16;
    float4 w0 = make_float4(o[0] * inv, o[1] * inv, o[2] * inv, o[3] * inv);
    float4 w1 = make_float4(o[4] * inv, o[5] * inv, o[6] * inv, o[7] * inv);
    float4 w2 = make_float4(o[8] * inv, o[9] * inv, o[10] * inv, o[11] * inv);
    float4 w3 = make_float4(o[12] * inv, o[13] * inv, o[14] * inv, o[15] * inv);
    *(float4*)&op[0] = w0;
    *(float4*)&op[4] = w1;
    *(float4*)&op[8] = w2;
    *(float4*)&op[12] = w3;
}

// ---------------------------------------------------------------------------
extern "C" void kernel_launch(void* const* d_in, const int* in_sizes, int n_in,
                              void* d_out, int out_size)
{
    const float* x    = (const float*)d_in[0];
    const float* cosT = (const float*)d_in[1];
    const float* sinT = (const float*)d_in[2];
    const float* wq   = (const float*)d_in[3];
    const float* bq   = (const float*)d_in[4];
    const float* wk   = (const float*)d_in[5];
    const float* bk   = (const float*)d_in[6];
    const float* wv   = (const float*)d_in[7];
    const float* bv   = (const float*)d_in[8];
    const float* wo   = (const float*)d_in[9];
    const float* bo   = (const float*)d_in[10];
    // d_in[11] = mask (unused; causal mask computed analytically)

    float* out  = (float*)d_out;                        // (B, T, D)      8388608
    float* kout = out + (size_t)8388608;                // (B, KV, T, HD) 2097152
    float* vout = out + (size_t)10485760;               // (B, KV, T, HD) 2097152

    const int M = 2 * T_SEQ;  // 4096
    dim3 blk(256);

    // Q projection + RoPE -> g_q
    gemm_kernel<1><<<dim3(DMODEL / GBN, M / GBM), blk>>>(
        x, wq, bq, nullptr, cosT, sinT, M, NH * HD, DMODEL);
    // K projection + RoPE -> kout (b, kv, t, d)
    gemm_kernel<2><<<dim3((NKV * HD) / GBN, M / GBM), blk>>>(
        x, wk, bk, kout, cosT, sinT, M, NKV * HD, DMODEL);
    // V projection -> vout (b, kv, t, d)
    gemm_kernel<3><<<dim3((NKV * HD) / GBN, M / GBM), blk>>>(
        x, wv, bv, vout, nullptr, nullptr, M, NKV * HD, DMODEL);
    // Attention -> g_ctx
    attn_kernel<<<dim3(T_SEQ / 64, 2 * NH), blk>>>(kout, vout);
    // Output projection -> out
    gemm_kernel<0><<<dim3(DMODEL / GBN, M / GBM), blk>>>(
        nullptr, wo, bo, out, nullptr, nullptr, M, DMODEL, DMODEL);
}

// round 3
// speedup vs baseline: 1.3116x; 1.3116x over previous
#include <cuda_runtime.h>
#include <cstdint>
#include <math.h>

#define T_SEQ 2048
#define DMODEL 2048
#define NH 32
#define NKV 8
#define HD 64

// Scratch (device globals: allocation-free per harness rules)
__device__ float g_q[(size_t)2 * NH * T_SEQ * HD];    // (b, h, t, d)
__device__ float g_ctx[(size_t)2 * T_SEQ * NH * HD];  // (b, t, h, d)

__device__ __forceinline__ uint32_t f2tf32(float f) {
    uint32_t u;
    asm("cvt.rna.tf32.f32 %0, %1;" : "=r"(u) : "f"(f));
    return u;
}

__device__ __forceinline__ void mma_tf32(float* c, uint32_t a0, uint32_t a1,
                                         uint32_t a2, uint32_t a3,
                                         uint32_t b0, uint32_t b1) {
    asm volatile(
        "mma.sync.aligned.m16n8k8.row.col.f32.tf32.tf32.f32 "
        "{%0,%1,%2,%3}, {%4,%5,%6,%7}, {%8,%9}, {%0,%1,%2,%3};"
        : "+f"(c[0]), "+f"(c[1]), "+f"(c[2]), "+f"(c[3])
        : "r"(a0), "r"(a1), "r"(a2), "r"(a3), "r"(b0), "r"(b1));
}

// ============================================================================
// tf32 mma.sync GEMM: C = A(MxK) * W(NxK)^T + bias, fused epilogues.
// Block tile 128x128, BK=32 (single-buffered smem, register prefetch).
// 8 warps, 2x4 layout; warp tile 64x32; per warp 4x4 m16n8k8 fragments.
// Fragment k within each 8-group is relabeled (applied identically to A and
// B, so the dot product is unchanged) so that (tig, tig+4) sits at
// contiguous words -> one 64-bit LDS per fragment pair. Pad = 40 words/row
// makes all fragment loads and tile stores bank-conflict-free.
// MODE 0: A := g_ctx, plain write C[m*N+n]            (output projection)
// MODE 1: RoPE, write g_q as (b, h, t, d)             (Q projection)
// MODE 2: RoPE, write C as (b, kv, t, d)              (K projection)
// MODE 3: plain, write C as (b, kv, t, d)             (V projection)
// ============================================================================
#define SPAD 40

template <int MODE>
__global__ __launch_bounds__(256) void mma_gemm(
    const float* __restrict__ A, const float* __restrict__ W,
    const float* __restrict__ bias, float* __restrict__ C,
    const float* __restrict__ cosT, const float* __restrict__ sinT,
    int M, int N, int K)
{
    __shared__ __align__(16) uint32_t As[128 * SPAD];
    __shared__ __align__(16) uint32_t Bs[128 * SPAD];

    const int tid = threadIdx.x;
    const int wid = tid >> 5;
    const int lane = tid & 31;
    const int gr = lane >> 2;   // groupID (0..7)
    const int tig = lane & 3;   // thread-in-group (0..3)
    const int wm = wid >> 2;    // warp row (0..1)
    const int wn = wid & 3;     // warp col (0..3)

    const int m0 = blockIdx.y * 128;
    const int n0 = blockIdx.x * 128;
    const float* Ap = (MODE == 0) ? g_ctx : A;

    // Global->smem assignment: 4 float4 per thread per tile.
    const int rbase = tid >> 3;      // 0..31
    const int cg = tid & 7;          // 16B column group
    const float* Arow[4];
    const float* Wrow[4];
    uint32_t soff[4];
#pragma unroll
    for (int i = 0; i < 4; i++) {
        Arow[i] = Ap + (size_t)(m0 + i * 32 + rbase) * K + cg * 4;
        Wrow[i] = W + (size_t)(n0 + i * 32 + rbase) * K + cg * 4;
        soff[i] = (uint32_t)((i * 32 + rbase) * SPAD + cg * 4);
    }

    float4 pa[4], pb[4];
#pragma unroll
    for (int i = 0; i < 4; i++) {
        pa[i] = *(const float4*)Arow[i];
        pb[i] = *(const float4*)Wrow[i];
    }

    float acc[4][4][4];
#pragma unroll
    for (int mi = 0; mi < 4; mi++)
#pragma unroll
        for (int ni = 0; ni < 4; ni++)
#pragma unroll
            for (int r = 0; r < 4; r++) acc[mi][ni][r] = 0.f;

    const uint32_t* Abase = As + (wm * 64) * SPAD;
    const uint32_t* Bbase = Bs + (wn * 32) * SPAD;

    const int NST = K / 32;
    for (int s = 0; s < NST; s++) {
        // store prefetched stage (fp32 -> tf32 bits)
#pragma unroll
        for (int i = 0; i < 4; i++) {
            uint4 ua, ub;
            ua.x = f2tf32(pa[i].x); ua.y = f2tf32(pa[i].y);
            ua.z = f2tf32(pa[i].z); ua.w = f2tf32(pa[i].w);
            ub.x = f2tf32(pb[i].x); ub.y = f2tf32(pb[i].y);
            ub.z = f2tf32(pb[i].z); ub.w = f2tf32(pb[i].w);
            *(uint4*)&As[soff[i]] = ua;
            *(uint4*)&Bs[soff[i]] = ub;
        }
        if (s + 1 < NST) {
#pragma unroll
            for (int i = 0; i < 4; i++) {
                Arow[i] += 32;
                Wrow[i] += 32;
                pa[i] = *(const float4*)Arow[i];
                pb[i] = *(const float4*)Wrow[i];
            }
        }
        __syncthreads();

#pragma unroll
        for (int kk = 0; kk < 4; kk++) {
            const int kc = kk * 8 + 2 * tig;  // relabeled k pair (tig, tig+4)
            uint32_t bf[4][2];
#pragma unroll
            for (int ni = 0; ni < 4; ni++) {
                uint64_t bv = *(const uint64_t*)&Bbase[(ni * 8 + gr) * SPAD + kc];
                bf[ni][0] = (uint32_t)bv;
                bf[ni][1] = (uint32_t)(bv >> 32);
            }
#pragma unroll
            for (int mi = 0; mi < 4; mi++) {
                uint64_t a02 = *(const uint64_t*)&Abase[(mi * 16 + gr) * SPAD + kc];
                uint64_t a13 = *(const uint64_t*)&Abase[(mi * 16 + gr + 8) * SPAD + kc];
                uint32_t a0 = (uint32_t)a02, a2 = (uint32_t)(a02 >> 32);
                uint32_t a1 = (uint32_t)a13, a3 = (uint32_t)(a13 >> 32);
#pragma unroll
                for (int ni = 0; ni < 4; ni++)
                    mma_tf32(acc[mi][ni], a0, a1, a2, a3, bf[ni][0], bf[ni][1]);
            }
        }
        __syncthreads();
    }

    // ---------------- Register epilogue ----------------
#pragma unroll
    for (int mi = 0; mi < 4; mi++) {
#pragma unroll
        for (int half = 0; half < 2; half++) {
            const int m = m0 + wm * 64 + mi * 16 + gr + half * 8;
            const int bb = m >> 11;
            const int t = m & (T_SEQ - 1);
#pragma unroll
            for (int ni = 0; ni < 4; ni++) {
                const int n = n0 + wn * 32 + ni * 8 + tig * 2;
                float v0 = acc[mi][ni][half * 2 + 0] + bias[n];
                float v1 = acc[mi][ni][half * 2 + 1] + bias[n + 1];
                if (MODE == 1 || MODE == 2) {
                    const int hh = (n & 63) >> 1;
                    const float c = cosT[t * (HD / 2) + hh];
                    const float ss = sinT[t * (HD / 2) + hh];
                    const float e = v0 * c - v1 * ss;
                    const float o = v0 * ss + v1 * c;
                    v0 = e;
                    v1 = o;
                }
                float2 wv = make_float2(v0, v1);
                if (MODE == 0) {
                    *(float2*)&C[(size_t)m * N + n] = wv;
                } else if (MODE == 1) {
                    *(float2*)&g_q[(((size_t)(bb * NH + (n >> 6))) * T_SEQ + t) * HD + (n & 63)] = wv;
                } else {
                    *(float2*)&C[(((size_t)(bb * NKV + (n >> 6))) * T_SEQ + t) * HD + (n & 63)] = wv;
                }
            }
        }
    }
}

// ---------------------------------------------------------------------------
// Causal GQA flash attention (fp32). Unchanged (known correct).
// ---------------------------------------------------------------------------
__global__ __launch_bounds__(256) void attn_kernel(const float* __restrict__ Kg,
                                                   const float* __restrict__ Vg)
{
    __shared__ float Qt[64 * 64];
    __shared__ float Kt[64 * 64];
    __shared__ float Vs[64 * 64];

    int tid = threadIdx.x;
    int r = tid >> 2;
    int quad = tid & 3;

    int qi = blockIdx.x;
    int bh = blockIdx.y;
    int b = bh >> 5;
    int h = bh & 31;
    int kvh = h >> 2;

    const float* Qg = g_q + (((size_t)(b * NH + h)) * T_SEQ + qi * 64) * HD;
    const float* Kb = Kg + ((size_t)(b * NKV + kvh)) * T_SEQ * HD;
    const float* Vb = Vg + ((size_t)(b * NKV + kvh)) * T_SEQ * HD;

#pragma unroll
    for (int it = 0; it < 4; it++) {
        int lin = it * 256 + tid;
        int d4 = (lin >> 6) << 2;
        int rr = lin & 63;
        float4 v = *(const float4*)&Qg[rr * HD + d4];
        Qt[(d4 + 0) * 64 + rr] = v.x;
        Qt[(d4 + 1) * 64 + rr] = v.y;
        Qt[(d4 + 2) * 64 + rr] = v.z;
        Qt[(d4 + 3) * 64 + rr] = v.w;
    }

    float o[16];
#pragma unroll
    for (int j = 0; j < 16; j++) o[j] = 0.f;
    float mrun = -INFINITY;
    float lrun = 0.f;

    for (int jt = 0; jt <= qi; jt++) {
        __syncthreads();
        const float* Kp = Kb + (size_t)jt * 64 * HD;
        const float* Vp = Vb + (size_t)jt * 64 * HD;
#pragma unroll
        for (int it = 0; it < 4; it++) {
            int lin = it * 256 + tid;
            int d4 = (lin >> 6) << 2;
            int rr = lin & 63;
            float4 kv = *(const float4*)&Kp[rr * HD + d4];
            Kt[(d4 + 0) * 64 + rr] = kv.x;
            Kt[(d4 + 1) * 64 + rr] = kv.y;
            Kt[(d4 + 2) * 64 + rr] = kv.z;
            Kt[(d4 + 3) * 64 + rr] = kv.w;
            float4 vv = *(const float4*)&Vp[rr * HD + d4];
            *(float4*)&Vs[rr * 64 + d4] = vv;
        }
        __syncthreads();

        float p[16];
#pragma unroll
        for (int j = 0; j < 16; j++) p[j] = 0.f;
        const float* KtQ = Kt + quad * 16;
#pragma unroll 8
        for (int k = 0; k < 64; k++) {
            float qv = Qt[k * 64 + r];
            float4 a0 = *(const float4*)&KtQ[k * 64 + 0];
            float4 a1 = *(const float4*)&KtQ[k * 64 + 4];
            float4 a2 = *(const float4*)&KtQ[k * 64 + 8];
            float4 a3 = *(const float4*)&KtQ[k * 64 + 12];
            p[0] += qv * a0.x;  p[1] += qv * a0.y;  p[2] += qv * a0.z;  p[3] += qv * a0.w;
            p[4] += qv * a1.x;  p[5] += qv * a1.y;  p[6] += qv * a1.z;  p[7] += qv * a1.w;
            p[8] += qv * a2.x;  p[9] += qv * a2.y;  p[10] += qv * a2.z; p[11] += qv * a2.w;
            p[12] += qv * a3.x; p[13] += qv * a3.y; p[14] += qv * a3.z; p[15] += qv * a3.w;
        }

        bool diag = (jt == qi);
        float smax = -INFINITY;
#pragma unroll
        for (int j = 0; j < 16; j++) {
            float sv = p[j] * 0.125f;
            if (diag && (quad * 16 + j) > r) sv = -INFINITY;
            p[j] = sv;
            smax = fmaxf(smax, sv);
        }
        smax = fmaxf(smax, __shfl_xor_sync(0xffffffffu, smax, 1, 4));
        smax = fmaxf(smax, __shfl_xor_sync(0xffffffffu, smax, 2, 4));
        float mnew = fmaxf(mrun, smax);
        float alpha = __expf(mrun - mnew);
        float ls = 0.f;
#pragma unroll
        for (int j = 0; j < 16; j++) {
            p[j] = __expf(p[j] - mnew);
            ls += p[j];
        }
        ls += __shfl_xor_sync(0xffffffffu, ls, 1, 4);
        ls += __shfl_xor_sync(0xffffffffu, ls, 2, 4);
        lrun = lrun * alpha + ls;
        mrun = mnew;
#pragma unroll
        for (int j = 0; j < 16; j++) o[j] *= alpha;

        const float* VsQ = Vs + quad * 16;
#pragma unroll
        for (int s = 0; s < 64; s++) {
            float pv = __shfl_sync(0xffffffffu, p[s & 15], s >> 4, 4);
            float4 v0 = *(const float4*)&VsQ[s * 64 + 0];
            float4 v1 = *(const float4*)&VsQ[s * 64 + 4];
            float4 v2 = *(const float4*)&VsQ[s * 64 + 8];
            float4 v3 = *(const float4*)&VsQ[s * 64 + 12];
            o[0] += pv * v0.x;  o[1] += pv * v0.y;  o[2] += pv * v0.z;  o[3] += pv * v0.w;
            o[4] += pv * v1.x;  o[5] += pv * v1.y;  o[6] += pv * v1.z;  o[7] += pv * v1.w;
            o[8] += pv * v2.x;  o[9] += pv * v2.y;  o[10] += pv * v2.z; o[11] += pv * v2.w;
            o[12] += pv * v3.x; o[13] += pv * v3.y; o[14] += pv * v3.z; o[15] += pv * v3.w;
        }
    }

    float inv = 1.0f / lrun;
    int t = qi * 64 + r;
    float* op = g_ctx + (((size_t)(b * T_SEQ + t)) * NH + h) * HD + quad * 16;
    float4 w0 = make_float4(o[0] * inv, o[1] * inv, o[2] * inv, o[3] * inv);
    float4 w1 = make_float4(o[4] * inv, o[5] * inv, o[6] * inv, o[7] * inv);
    float4 w2 = make_float4(o[8] * inv, o[9] * inv, o[10] * inv, o[11] * inv);
    float4 w3 = make_float4(o[12] * inv, o[13] * inv, o[14] * inv, o[15] * inv);
    *(float4*)&op[0] = w0;
    *(float4*)&op[4] = w1;
    *(float4*)&op[8] = w2;
    *(float4*)&op[12] = w3;
}

// ---------------------------------------------------------------------------
extern "C" void kernel_launch(void* const* d_in, const int* in_sizes, int n_in,
                              void* d_out, int out_size)
{
    const float* x    = (const float*)d_in[0];
    const float* cosT = (const float*)d_in[1];
    const float* sinT = (const float*)d_in[2];
    const float* wq   = (const float*)d_in[3];
    const float* bq   = (const float*)d_in[4];
    const float* wk   = (const float*)d_in[5];
    const float* bk   = (const float*)d_in[6];
    const float* wv   = (const float*)d_in[7];
    const float* bv   = (const float*)d_in[8];
    const float* wo   = (const float*)d_in[9];
    const float* bo   = (const float*)d_in[10];
    // d_in[11] = mask (unused; causal mask computed analytically)

    float* out  = (float*)d_out;            // (B, T, D)
    float* kout = out + (size_t)8388608;    // (B, KV, T, HD)
    float* vout = out + (size_t)10485760;   // (B, KV, T, HD)

    const int M = 2 * T_SEQ;  // 4096
    dim3 blk(256);

    // Q projection + RoPE -> g_q
    mma_gemm<1><<<dim3(DMODEL / 128, M / 128), blk>>>(
        x, wq, bq, nullptr, cosT, sinT, M, NH * HD, DMODEL);
    // K projection + RoPE -> kout (b, kv, t, d)
    mma_gemm<2><<<dim3((NKV * HD) / 128, M / 128), blk>>>(
        x, wk, bk, kout, cosT, sinT, M, NKV * HD, DMODEL);
    // V projection -> vout (b, kv, t, d)
    mma_gemm<3><<<dim3((NKV * HD) / 128, M / 128), blk>>>(
        x, wv, bv, vout, nullptr, nullptr, M, NKV * HD, DMODEL);
    // Attention -> g_ctx
    attn_kernel<<<dim3(T_SEQ / 64, 2 * NH), blk>>>(kout, vout);
    // Output projection -> out
    mma_gemm<0><<<dim3(DMODEL / 128, M / 128), blk>>>(
        nullptr, wo, bo, out, nullptr, nullptr, M, DMODEL, DMODEL);
}

// round 4
// speedup vs baseline: 5.8505x; 4.4605x over previous
#include <cuda_runtime.h>
#include <cstdint>
#include <math.h>

#define T_SEQ 2048
#define DMODEL 2048
#define NH 32
#define NKV 8
#define HD 64

// Scratch (device globals: allocation-free per harness rules)
__device__ float g_q[(size_t)2 * NH * T_SEQ * HD];    // (b, h, t, d)
__device__ float g_ctx[(size_t)2 * T_SEQ * NH * HD];  // (b, t, h, d)

__device__ __forceinline__ uint32_t f2tf32(float f) {
    uint32_t u;
    asm("cvt.rna.tf32.f32 %0, %1;" : "=r"(u) : "f"(f));
    return u;
}

__device__ __forceinline__ void mma_tf32(float* c, uint32_t a0, uint32_t a1,
                                         uint32_t a2, uint32_t a3,
                                         uint32_t b0, uint32_t b1) {
    asm volatile(
        "mma.sync.aligned.m16n8k8.row.col.f32.tf32.tf32.f32 "
        "{%0,%1,%2,%3}, {%4,%5,%6,%7}, {%8,%9}, {%0,%1,%2,%3};"
        : "+f"(c[0]), "+f"(c[1]), "+f"(c[2]), "+f"(c[3])
        : "r"(a0), "r"(a1), "r"(a2), "r"(a3), "r"(b0), "r"(b1));
}

// k-index permutation within an 8-block: j -> ((j&3)<<1)|(j>>2), so that the
// mma k-pair (tig, tig+4) lands on adjacent words (one LDS.64). Applied
// identically to both operands' k dimension -> dot product unchanged.
__device__ __forceinline__ int kperm(int j) { return ((j & 3) << 1) | (j >> 2); }

// ============================================================================
// tf32 mma.sync GEMM (unchanged from R3, passing): C = A*W^T + bias, epilogues.
// ============================================================================
#define SPAD 40

template <int MODE>
__global__ __launch_bounds__(256) void mma_gemm(
    const float* __restrict__ A, const float* __restrict__ W,
    const float* __restrict__ bias, float* __restrict__ C,
    const float* __restrict__ cosT, const float* __restrict__ sinT,
    int M, int N, int K)
{
    __shared__ __align__(16) uint32_t As[128 * SPAD];
    __shared__ __align__(16) uint32_t Bs[128 * SPAD];

    const int tid = threadIdx.x;
    const int wid = tid >> 5;
    const int lane = tid & 31;
    const int gr = lane >> 2;
    const int tig = lane & 3;
    const int wm = wid >> 2;
    const int wn = wid & 3;

    const int m0 = blockIdx.y * 128;
    const int n0 = blockIdx.x * 128;
    const float* Ap = (MODE == 0) ? g_ctx : A;

    const int rbase = tid >> 3;
    const int cg = tid & 7;
    const float* Arow[4];
    const float* Wrow[4];
    uint32_t soff[4];
#pragma unroll
    for (int i = 0; i < 4; i++) {
        Arow[i] = Ap + (size_t)(m0 + i * 32 + rbase) * K + cg * 4;
        Wrow[i] = W + (size_t)(n0 + i * 32 + rbase) * K + cg * 4;
        soff[i] = (uint32_t)((i * 32 + rbase) * SPAD + cg * 4);
    }

    float4 pa[4], pb[4];
#pragma unroll
    for (int i = 0; i < 4; i++) {
        pa[i] = *(const float4*)Arow[i];
        pb[i] = *(const float4*)Wrow[i];
    }

    float acc[4][4][4];
#pragma unroll
    for (int mi = 0; mi < 4; mi++)
#pragma unroll
        for (int ni = 0; ni < 4; ni++)
#pragma unroll
            for (int r = 0; r < 4; r++) acc[mi][ni][r] = 0.f;

    const uint32_t* Abase = As + (wm * 64) * SPAD;
    const uint32_t* Bbase = Bs + (wn * 32) * SPAD;

    const int NST = K / 32;
    for (int s = 0; s < NST; s++) {
#pragma unroll
        for (int i = 0; i < 4; i++) {
            uint4 ua, ub;
            ua.x = f2tf32(pa[i].x); ua.y = f2tf32(pa[i].y);
            ua.z = f2tf32(pa[i].z); ua.w = f2tf32(pa[i].w);
            ub.x = f2tf32(pb[i].x); ub.y = f2tf32(pb[i].y);
            ub.z = f2tf32(pb[i].z); ub.w = f2tf32(pb[i].w);
            *(uint4*)&As[soff[i]] = ua;
            *(uint4*)&Bs[soff[i]] = ub;
        }
        if (s + 1 < NST) {
#pragma unroll
            for (int i = 0; i < 4; i++) {
                Arow[i] += 32;
                Wrow[i] += 32;
                pa[i] = *(const float4*)Arow[i];
                pb[i] = *(const float4*)Wrow[i];
            }
        }
        __syncthreads();

#pragma unroll
        for (int kk = 0; kk < 4; kk++) {
            const int kc = kk * 8 + 2 * tig;
            uint32_t bf[4][2];
#pragma unroll
            for (int ni = 0; ni < 4; ni++) {
                uint64_t bv = *(const uint64_t*)&Bbase[(ni * 8 + gr) * SPAD + kc];
                bf[ni][0] = (uint32_t)bv;
                bf[ni][1] = (uint32_t)(bv >> 32);
            }
#pragma unroll
            for (int mi = 0; mi < 4; mi++) {
                uint64_t a02 = *(const uint64_t*)&Abase[(mi * 16 + gr) * SPAD + kc];
                uint64_t a13 = *(const uint64_t*)&Abase[(mi * 16 + gr + 8) * SPAD + kc];
                uint32_t a0 = (uint32_t)a02, a2 = (uint32_t)(a02 >> 32);
                uint32_t a1 = (uint32_t)a13, a3 = (uint32_t)(a13 >> 32);
#pragma unroll
                for (int ni = 0; ni < 4; ni++)
                    mma_tf32(acc[mi][ni], a0, a1, a2, a3, bf[ni][0], bf[ni][1]);
            }
        }
        __syncthreads();
    }

#pragma unroll
    for (int mi = 0; mi < 4; mi++) {
#pragma unroll
        for (int half = 0; half < 2; half++) {
            const int m = m0 + wm * 64 + mi * 16 + gr + half * 8;
            const int bb = m >> 11;
            const int t = m & (T_SEQ - 1);
#pragma unroll
            for (int ni = 0; ni < 4; ni++) {
                const int n = n0 + wn * 32 + ni * 8 + tig * 2;
                float v0 = acc[mi][ni][half * 2 + 0] + bias[n];
                float v1 = acc[mi][ni][half * 2 + 1] + bias[n + 1];
                if (MODE == 1 || MODE == 2) {
                    const int hh = (n & 63) >> 1;
                    const float c = cosT[t * (HD / 2) + hh];
                    const float ss = sinT[t * (HD / 2) + hh];
                    const float e = v0 * c - v1 * ss;
                    const float o = v0 * ss + v1 * c;
                    v0 = e;
                    v1 = o;
                }
                float2 wv = make_float2(v0, v1);
                if (MODE == 0) {
                    *(float2*)&C[(size_t)m * N + n] = wv;
                } else if (MODE == 1) {
                    *(float2*)&g_q[(((size_t)(bb * NH + (n >> 6))) * T_SEQ + t) * HD + (n & 63)] = wv;
                } else {
                    *(float2*)&C[(((size_t)(bb * NKV + (n >> 6))) * T_SEQ + t) * HD + (n & 63)] = wv;
                }
            }
        }
    }
}

// ============================================================================
// Flash attention with tf32 mma.sync.
// Q tile 128 (grid.x = 16), key tile 64, 8 warps: warp w owns S rows
// [16w, 16w+16) x all 64 keys. Q A-frags in registers (pre-scaled 1/8).
// K in smem [key][perm(d)] pitch 68; V transposed [d][perm(key)] pitch 72.
// P->A fragment remap via width-4 shuffles (no smem round trip).
// ============================================================================
#define PKS 68
#define PVT 72

__global__ __launch_bounds__(256) void attn_mma(const float* __restrict__ Kg,
                                                const float* __restrict__ Vg)
{
    __shared__ __align__(16) uint32_t Ks[64 * PKS];
    __shared__ __align__(16) uint32_t Vt[64 * PVT];

    const int tid = threadIdx.x;
    const int wid = tid >> 5;
    const int lane = tid & 31;
    const int gr = lane >> 2;
    const int tig = lane & 3;

    const int qt = blockIdx.x;
    const int bh = blockIdx.y;
    const int b = bh >> 5;
    const int h = bh & 31;
    const int kvh = h >> 2;

    // ---- Q fragments (rows 16*wid + gr / +8), scaled by 1/sqrt(64) ----
    const float* Qg = g_q + (((size_t)(b * NH + h)) * T_SEQ + qt * 128 + wid * 16) * HD;
    uint32_t qa[8][4];
#pragma unroll
    for (int ks = 0; ks < 8; ks++) {
        qa[ks][0] = f2tf32(Qg[gr * HD + 8 * ks + tig] * 0.125f);
        qa[ks][1] = f2tf32(Qg[(gr + 8) * HD + 8 * ks + tig] * 0.125f);
        qa[ks][2] = f2tf32(Qg[gr * HD + 8 * ks + tig + 4] * 0.125f);
        qa[ks][3] = f2tf32(Qg[(gr + 8) * HD + 8 * ks + tig + 4] * 0.125f);
    }

    const float* Kb = Kg + ((size_t)(b * NKV + kvh)) * T_SEQ * HD;
    const float* Vb = Vg + ((size_t)(b * NKV + kvh)) * T_SEQ * HD;

    float ctx[8][4];
#pragma unroll
    for (int ni = 0; ni < 8; ni++)
#pragma unroll
        for (int r = 0; r < 4; r++) ctx[ni][r] = 0.f;
    float mrun0 = -INFINITY, mrun1 = -INFINITY;
    float lrun0 = 0.f, lrun1 = 0.f;

    // loader indices
    const int lkey = tid >> 2;              // K loader: key 0..63
    const int ldseg = (tid & 3) * 16;       // K loader: d segment
    const int vkey = tid & 63;              // V loader: key
    const int vds = (tid >> 6) * 16;        // V loader: d block
    const int vpk = ((vkey >> 3) << 3) | kperm(vkey & 7);

    const int row0 = qt * 128 + wid * 16 + gr;  // global q rows of this thread
    const int row1 = row0 + 8;

    const int njt = 2 * qt + 2;
    for (int jt = 0; jt < njt; jt++) {
        __syncthreads();
        const float* Kp = Kb + (size_t)jt * 64 * HD;
        const float* Vp = Vb + (size_t)jt * 64 * HD;
        // K tile -> Ks[key][perm(d)]
#pragma unroll
        for (int c = 0; c < 4; c++) {
            const int d0 = ldseg + 4 * c;
            float4 v = *(const float4*)&Kp[lkey * HD + d0];
            const int blk = (d0 >> 3) << 3;
            const int j0 = d0 & 7;
            uint32_t* kr = &Ks[lkey * PKS + blk];
            kr[kperm(j0 + 0)] = f2tf32(v.x);
            kr[kperm(j0 + 1)] = f2tf32(v.y);
            kr[kperm(j0 + 2)] = f2tf32(v.z);
            kr[kperm(j0 + 3)] = f2tf32(v.w);
        }
        // V tile -> Vt[d][perm(key)]
#pragma unroll
        for (int c = 0; c < 4; c++) {
            const int d0 = vds + 4 * c;
            float4 v = *(const float4*)&Vp[vkey * HD + d0];
            Vt[(d0 + 0) * PVT + vpk] = f2tf32(v.x);
            Vt[(d0 + 1) * PVT + vpk] = f2tf32(v.y);
            Vt[(d0 + 2) * PVT + vpk] = f2tf32(v.z);
            Vt[(d0 + 3) * PVT + vpk] = f2tf32(v.w);
        }
        __syncthreads();

        // Fully-masked warp x tile: skip compute.
        if (jt == 2 * qt + 1 && wid < 4) continue;

        // ---- S = Q K^T (warp tile 16 x 64) ----
        float s[8][4];
#pragma unroll
        for (int ni = 0; ni < 8; ni++)
#pragma unroll
            for (int r = 0; r < 4; r++) s[ni][r] = 0.f;
#pragma unroll
        for (int ks = 0; ks < 8; ks++) {
#pragma unroll
            for (int ni = 0; ni < 8; ni++) {
                uint64_t bv = *(const uint64_t*)&Ks[(ni * 8 + gr) * PKS + ks * 8 + 2 * tig];
                mma_tf32(s[ni], qa[ks][0], qa[ks][1], qa[ks][2], qa[ks][3],
                         (uint32_t)bv, (uint32_t)(bv >> 32));
            }
        }

        // ---- causal mask (only tiles touching the diagonal) ----
        if (jt >= 2 * qt) {
            const int colb = jt * 64 + 2 * tig;
#pragma unroll
            for (int ni = 0; ni < 8; ni++) {
                const int c0 = colb + 8 * ni;
                if (c0 > row0) s[ni][0] = -INFINITY;
                if (c0 + 1 > row0) s[ni][1] = -INFINITY;
                if (c0 > row1) s[ni][2] = -INFINITY;
                if (c0 + 1 > row1) s[ni][3] = -INFINITY;
            }
        }

        // ---- online softmax (rows gr, gr+8; stats across tig group) ----
        float m0 = -INFINITY, m1 = -INFINITY;
#pragma unroll
        for (int ni = 0; ni < 8; ni++) {
            m0 = fmaxf(m0, fmaxf(s[ni][0], s[ni][1]));
            m1 = fmaxf(m1, fmaxf(s[ni][2], s[ni][3]));
        }
        m0 = fmaxf(m0, __shfl_xor_sync(0xffffffffu, m0, 1, 4));
        m0 = fmaxf(m0, __shfl_xor_sync(0xffffffffu, m0, 2, 4));
        m1 = fmaxf(m1, __shfl_xor_sync(0xffffffffu, m1, 1, 4));
        m1 = fmaxf(m1, __shfl_xor_sync(0xffffffffu, m1, 2, 4));
        const float mn0 = fmaxf(mrun0, m0);
        const float mn1 = fmaxf(mrun1, m1);
        const float al0 = __expf(mrun0 - mn0);
        const float al1 = __expf(mrun1 - mn1);
        float ls0 = 0.f, ls1 = 0.f;
        uint32_t pb[8][4];
#pragma unroll
        for (int ni = 0; ni < 8; ni++) {
            float p0 = __expf(s[ni][0] - mn0);
            float p1 = __expf(s[ni][1] - mn0);
            float p2 = __expf(s[ni][2] - mn1);
            float p3 = __expf(s[ni][3] - mn1);
            ls0 += p0 + p1;
            ls1 += p2 + p3;
            pb[ni][0] = f2tf32(p0);
            pb[ni][1] = f2tf32(p1);
            pb[ni][2] = f2tf32(p2);
            pb[ni][3] = f2tf32(p3);
            ctx[ni][0] *= al0;
            ctx[ni][1] *= al0;
            ctx[ni][2] *= al1;
            ctx[ni][3] *= al1;
        }
        ls0 += __shfl_xor_sync(0xffffffffu, ls0, 1, 4);
        ls0 += __shfl_xor_sync(0xffffffffu, ls0, 2, 4);
        ls1 += __shfl_xor_sync(0xffffffffu, ls1, 1, 4);
        ls1 += __shfl_xor_sync(0xffffffffu, ls1, 2, 4);
        mrun0 = mn0;
        mrun1 = mn1;
        lrun0 = lrun0 * al0 + ls0;
        lrun1 = lrun1 * al1 + ls1;

        // ---- ctx += P V (P remapped C->A via width-4 shuffles) ----
        const int sl0 = tig >> 1;
        const int sl1 = sl0 + 2;
        const bool odd = (tig & 1);
#pragma unroll
        for (int ks = 0; ks < 8; ks++) {
            uint32_t t0 = __shfl_sync(0xffffffffu, pb[ks][0], sl0, 4);
            uint32_t t1 = __shfl_sync(0xffffffffu, pb[ks][1], sl0, 4);
            uint32_t a0 = odd ? t1 : t0;
            t0 = __shfl_sync(0xffffffffu, pb[ks][0], sl1, 4);
            t1 = __shfl_sync(0xffffffffu, pb[ks][1], sl1, 4);
            uint32_t a2 = odd ? t1 : t0;
            t0 = __shfl_sync(0xffffffffu, pb[ks][2], sl0, 4);
            t1 = __shfl_sync(0xffffffffu, pb[ks][3], sl0, 4);
            uint32_t a1 = odd ? t1 : t0;
            t0 = __shfl_sync(0xffffffffu, pb[ks][2], sl1, 4);
            t1 = __shfl_sync(0xffffffffu, pb[ks][3], sl1, 4);
            uint32_t a3 = odd ? t1 : t0;
#pragma unroll
            for (int ni = 0; ni < 8; ni++) {
                uint64_t bv = *(const uint64_t*)&Vt[(ni * 8 + gr) * PVT + ks * 8 + 2 * tig];
                mma_tf32(ctx[ni], a0, a1, a2, a3, (uint32_t)bv, (uint32_t)(bv >> 32));
            }
        }
    }

    // ---- finalize & write g_ctx (b, t, h, d) ----
    const float inv0 = 1.0f / lrun0;
    const float inv1 = 1.0f / lrun1;
    float* o0 = g_ctx + (((size_t)(b * T_SEQ + row0)) * NH + h) * HD;
    float* o1 = g_ctx + (((size_t)(b * T_SEQ + row1)) * NH + h) * HD;
#pragma unroll
    for (int ni = 0; ni < 8; ni++) {
        const int d = ni * 8 + 2 * tig;
        *(float2*)&o0[d] = make_float2(ctx[ni][0] * inv0, ctx[ni][1] * inv0);
        *(float2*)&o1[d] = make_float2(ctx[ni][2] * inv1, ctx[ni][3] * inv1);
    }
}

// ---------------------------------------------------------------------------
extern "C" void kernel_launch(void* const* d_in, const int* in_sizes, int n_in,
                              void* d_out, int out_size)
{
    const float* x    = (const float*)d_in[0];
    const float* cosT = (const float*)d_in[1];
    const float* sinT = (const float*)d_in[2];
    const float* wq   = (const float*)d_in[3];
    const float* bq   = (const float*)d_in[4];
    const float* wk   = (const float*)d_in[5];
    const float* bk   = (const float*)d_in[6];
    const float* wv   = (const float*)d_in[7];
    const float* bv   = (const float*)d_in[8];
    const float* wo   = (const float*)d_in[9];
    const float* bo   = (const float*)d_in[10];

    float* out  = (float*)d_out;            // (B, T, D)
    float* kout = out + (size_t)8388608;    // (B, KV, T, HD)
    float* vout = out + (size_t)10485760;   // (B, KV, T, HD)

    const int M = 2 * T_SEQ;  // 4096
    dim3 blk(256);

    mma_gemm<1><<<dim3(DMODEL / 128, M / 128), blk>>>(
        x, wq, bq, nullptr, cosT, sinT, M, NH * HD, DMODEL);
    mma_gemm<2><<<dim3((NKV * HD) / 128, M / 128), blk>>>(
        x, wk, bk, kout, cosT, sinT, M, NKV * HD, DMODEL);
    mma_gemm<3><<<dim3((NKV * HD) / 128, M / 128), blk>>>(
        x, wv, bv, vout, nullptr, nullptr, M, NKV * HD, DMODEL);
    attn_mma<<<dim3(T_SEQ / 128, 2 * NH), blk>>>(kout, vout);
    mma_gemm<0><<<dim3(DMODEL / 128, M / 128), blk>>>(
        nullptr, wo, bo, out, nullptr, nullptr, M, DMODEL, DMODEL);
}